// round 12
// baseline (speedup 1.0000x reference)
#include <cuda_runtime.h>
#include <cstdint>
#include <cstddef>

#define NB   4
#define ZD   64
#define NK   400
#define TT   48000
#define CI   128
#define CO   128
#define KSZ  3
#define HH   32
#define TKC  120
#define NCH  (NB*NK)                 // 1600
#define RD   (CI*KSZ*CO)             // 49152

// ---------------- device scratch ----------------
__device__ float g_W[(size_t)NCH * RD];      // tf32-rounded weights [chunk][tap*CI+cin][co]
__device__ float g_hv[NCH * HH];
__device__ float g_bias[NCH * CO];

// ---------------- helpers ----------------
__device__ __forceinline__ uint32_t s2u(const void* p) {
    uint32_t a;
    asm("{ .reg .u64 t; cvta.to.shared.u64 t, %1; cvt.u32.u64 %0, t; }" : "=r"(a) : "l"(p));
    return a;
}
__device__ __forceinline__ void cp16(void* d, const void* s) {
    asm volatile("cp.async.cg.shared.global [%0], [%1], 16;" :: "r"(s2u(d)), "l"(s));
}
__device__ __forceinline__ void cp16z(void* d, const void* s, int sz) {
    asm volatile("cp.async.cg.shared.global [%0], [%1], 16, %2;" :: "r"(s2u(d)), "l"(s), "r"(sz));
}
__device__ __forceinline__ float to_tf32(float v) {
    uint32_t r;
    asm("cvt.rna.tf32.f32 %0, %1;" : "=r"(r) : "f"(v));
    return __uint_as_float(r);
}
__device__ __forceinline__ void mma_tf32(float* d, const uint32_t* a, uint32_t b0, uint32_t b1) {
    asm volatile(
        "mma.sync.aligned.m16n8k8.row.col.f32.tf32.tf32.f32 "
        "{%0,%1,%2,%3}, {%4,%5,%6,%7}, {%8,%9}, {%0,%1,%2,%3};"
        : "+f"(d[0]), "+f"(d[1]), "+f"(d[2]), "+f"(d[3])
        : "r"(a[0]), "r"(a[1]), "r"(a[2]), "r"(a[3]), "r"(b0), "r"(b1));
}

// ---------------------------------------------------------------------------
// Kernel 1: MLP hiddens + bias. 4 chunks/block, MLP weights staged in smem.
// ---------------------------------------------------------------------------
__global__ __launch_bounds__(256) void prep_kernel(
    const float* __restrict__ z,
    const float* __restrict__ w1, const float* __restrict__ b1,
    const float* __restrict__ bw1, const float* __restrict__ bb1,
    const float* __restrict__ bw2, const float* __restrict__ bb2)
{
    __shared__ float w1s[HH * ZD], bw1s[HH * ZD], bw2s[CO * HH];
    __shared__ float zv[4][ZD], hb[4][HH];
    int tid = threadIdx.x;
    for (int i = tid; i < HH * ZD; i += 256) { w1s[i] = w1[i]; bw1s[i] = bw1[i]; }
    for (int i = tid; i < CO * HH; i += 256) bw2s[i] = bw2[i];
    int c0 = blockIdx.x * 4;
    {
        int j = tid & 3, zi = tid >> 2;       // coalesced: consecutive kk per group
        int chunk = c0 + j, b = chunk / NK, kk = chunk % NK;
        zv[j][zi] = z[((size_t)b * ZD + zi) * NK + kk];
    }
    __syncthreads();
    if (tid < 128) {
        int j = tid >> 5, h = tid & 31;
        float s = b1[h];
        #pragma unroll 8
        for (int q = 0; q < ZD; q++) s += w1s[h * ZD + q] * zv[j][q];
        g_hv[(c0 + j) * HH + h] = fmaxf(s, 0.f);
    } else {
        int j = (tid - 128) >> 5, h = (tid - 128) & 31;
        float s = bb1[h];
        #pragma unroll 8
        for (int q = 0; q < ZD; q++) s += bw1s[h * ZD + q] * zv[j][q];
        hb[j][h] = fmaxf(s, 0.f);
    }
    __syncthreads();
    #pragma unroll
    for (int it = 0; it < 2; it++) {
        int idx = tid + it * 256;
        int j = idx >> 7, o = idx & 127;
        float s = bb2[o];
        #pragma unroll
        for (int q = 0; q < HH; q++) s += bw2s[o * HH + q] * hb[j][q];
        g_bias[(c0 + j) * CO + o] = s;
    }
}

// ---------------------------------------------------------------------------
// Kernel 2: weight-gen GEMM, tf32 mma, 3-term split (fp32-grade W, R9-exact):
//   W ~= w2h*hvh + w2l*hvh + w2h*hvl
// ---------------------------------------------------------------------------
#define WPD 136
#define WG_SMEM (4 * HH * WPD * 4)     // 69632 B dynamic
__global__ __launch_bounds__(256) void wgen_kernel(
    const float* __restrict__ w2, const float* __restrict__ b2)
{
    extern __shared__ __align__(16) float wsm[];
    float* ash = wsm;                   // [k=h][m=r] hi
    float* asl = wsm + HH * WPD;        // lo
    float* bsh = wsm + 2 * HH * WPD;    // [k=h][n=chunk] hi
    float* bsl = wsm + 3 * HH * WPD;    // lo
    int tid = threadIdx.x, lane = tid & 31, wid = tid >> 5;
    int lk = lane & 3, lg = lane >> 2;
    int r0 = blockIdx.x * 128;
    int c0 = blockIdx.y * 128;

    for (int i4 = tid; i4 < 1024; i4 += 256) {
        int r = i4 >> 3, h4 = i4 & 7;
        float4 v = *(const float4*)(w2 + (size_t)(r0 + r) * HH + h4 * 4);
        float f[4] = {v.x, v.y, v.z, v.w};
        #pragma unroll
        for (int q = 0; q < 4; q++) {
            float h = to_tf32(f[q]);
            ash[(h4 * 4 + q) * WPD + r] = h;
            asl[(h4 * 4 + q) * WPD + r] = to_tf32(f[q] - h);
        }
    }
    for (int i4 = tid; i4 < 1024; i4 += 256) {
        int c = i4 >> 3, h4 = i4 & 7;
        int cc = c0 + c; if (cc >= NCH) cc = NCH - 1;
        float4 v = *(const float4*)(g_hv + (size_t)cc * HH + h4 * 4);
        float f[4] = {v.x, v.y, v.z, v.w};
        #pragma unroll
        for (int q = 0; q < 4; q++) {
            float h = to_tf32(f[q]);
            bsh[(h4 * 4 + q) * WPD + c] = h;
            bsl[(h4 * 4 + q) * WPD + c] = to_tf32(f[q] - h);
        }
    }
    __syncthreads();

    int wrb = (wid >> 1) * 32;     // warp r base (m)
    int wcb = (wid & 1) * 64;      // warp chunk base (n)

    float acc[2][8][4];
    #pragma unroll
    for (int m = 0; m < 2; m++)
        #pragma unroll
        for (int n = 0; n < 8; n++)
            #pragma unroll
            for (int q = 0; q < 4; q++) acc[m][n][q] = 0.f;

    #pragma unroll
    for (int ks = 0; ks < 4; ks++) {
        uint32_t ah[2][4], al[2][4];
        const float* aph = ash + (ks * 8 + lk) * WPD + wrb + lg;
        const float* apl = asl + (ks * 8 + lk) * WPD + wrb + lg;
        #pragma unroll
        for (int m = 0; m < 2; m++) {
            const float* p = aph + m * 16;
            ah[m][0] = __float_as_uint(p[0]);
            ah[m][1] = __float_as_uint(p[8]);
            ah[m][2] = __float_as_uint(p[4 * WPD]);
            ah[m][3] = __float_as_uint(p[4 * WPD + 8]);
            const float* q = apl + m * 16;
            al[m][0] = __float_as_uint(q[0]);
            al[m][1] = __float_as_uint(q[8]);
            al[m][2] = __float_as_uint(q[4 * WPD]);
            al[m][3] = __float_as_uint(q[4 * WPD + 8]);
        }
        const float* bph = bsh + (ks * 8 + lk) * WPD + wcb + lg;
        const float* bpl = bsl + (ks * 8 + lk) * WPD + wcb + lg;
        #pragma unroll
        for (int n = 0; n < 8; n++) {
            uint32_t bh0 = __float_as_uint(bph[n * 8]);
            uint32_t bh1 = __float_as_uint(bph[4 * WPD + n * 8]);
            uint32_t bl0 = __float_as_uint(bpl[n * 8]);
            uint32_t bl1 = __float_as_uint(bpl[4 * WPD + n * 8]);
            #pragma unroll
            for (int m = 0; m < 2; m++) {
                mma_tf32(acc[m][n], ah[m], bh0, bh1);   // hi*hi
                mma_tf32(acc[m][n], al[m], bh0, bh1);   // lo*hi
                mma_tf32(acc[m][n], ah[m], bl0, bl1);   // hi*lo
            }
        }
    }

    // epilogue: + b2[r], rna-round, store g_W[c][r] (R9-proven scatter)
    float b2v[2][2];
    #pragma unroll
    for (int m = 0; m < 2; m++) {
        b2v[m][0] = b2[r0 + wrb + m * 16 + lg];
        b2v[m][1] = b2[r0 + wrb + m * 16 + lg + 8];
    }
    #pragma unroll
    for (int n = 0; n < 8; n++) {
        int c = c0 + wcb + n * 8 + 2 * lk;
        if (c < NCH) {
            float* base0 = g_W + (size_t)c * RD + r0 + wrb;
            float* base1 = base0 + RD;
            #pragma unroll
            for (int m = 0; m < 2; m++) {
                int rl = m * 16 + lg;
                base0[rl]     = to_tf32(acc[m][n][0] + b2v[m][0]);
                base1[rl]     = to_tf32(acc[m][n][1] + b2v[m][0]);
                base0[rl + 8] = to_tf32(acc[m][n][2] + b2v[m][1]);
                base1[rl + 8] = to_tf32(acc[m][n][3] + b2v[m][1]);
            }
        }
    }
}

// ---------------------------------------------------------------------------
// Kernel 3: conv via mma.sync tf32 (R9 structure; s=0 peeled, bias preloaded).
// 1 CTA/chunk, 256 thr (8 warps, 4co x 2t), 2 CTAs/SM. x tile rna-rounded in
// smem once; W streamed in 12 stages of [32 cin][128 co], double-buffered.
// ---------------------------------------------------------------------------
#define PD        136
#define WQ_FLOATS (32 * PD)                            // 4352
#define XS_FLOATS (128 * PD)                           // 17408
#define CONV_SMEM ((XS_FLOATS + 2 * WQ_FLOATS) * 4)    // 104448 B

__device__ __forceinline__ void conv_stage_mma(
    const float* __restrict__ wsb, const float* __restrict__ xs,
    float acc[2][8][4], int qq, int jo, int lk, int lg, int wcb, int wtb)
{
    const float* xrow0 = xs + (qq * 32 + lk) * PD;
    #pragma unroll
    for (int ks = 0; ks < 4; ks++) {
        uint32_t a[2][4];
        const float* ap = wsb + (ks * 8 + lk) * PD + wcb + lg;
        #pragma unroll
        for (int m = 0; m < 2; m++) {
            const float* p = ap + m * 16;
            a[m][0] = __float_as_uint(p[0]);
            a[m][1] = __float_as_uint(p[8]);
            a[m][2] = __float_as_uint(p[4 * PD]);
            a[m][3] = __float_as_uint(p[4 * PD + 8]);
        }
        const float* bp = xrow0 + ks * 8 * PD + wtb + lg + jo;
        #pragma unroll
        for (int n = 0; n < 8; n++) {
            uint32_t b0 = __float_as_uint(bp[n * 8]);
            uint32_t b1 = __float_as_uint(bp[4 * PD + n * 8]);
            mma_tf32(acc[0][n], a[0], b0, b1);
            mma_tf32(acc[1][n], a[1], b0, b1);
        }
    }
}

__global__ __launch_bounds__(256, 2) void conv_kernel(
    const float* __restrict__ x, float* __restrict__ out)
{
    extern __shared__ __align__(16) float sm[];
    float* xs = sm;                   // [128][PD], col j <-> t = t0 - 8 + j
    float* ws = sm + XS_FLOATS;       // [2][32][PD]

    int tid = threadIdx.x, lane = tid & 31, wid = tid >> 5;
    int lk = lane & 3, lg = lane >> 2;
    int wcb = (wid >> 1) * 32;        // warp co base
    int wtb = (wid & 1) * 64;         // warp t base
    int chunk = blockIdx.x;
    int b = chunk / NK, kk = chunk % NK;
    int t0 = kk * TKC;

    // ---- bias preload (independent; hides DRAM latency under staging) ----
    float biasv[2][2];
    #pragma unroll
    for (int m = 0; m < 2; m++) {
        biasv[m][0] = g_bias[(size_t)chunk * CO + wcb + m * 16 + lg];
        biasv[m][1] = g_bias[(size_t)chunk * CO + wcb + m * 16 + lg + 8];
    }

    // ---- stage x tile (raw fp32) + W stage 0 = group 0; W stage 1 = group 1 ----
    const float* xbase = x + (size_t)b * CI * TT;
    #pragma unroll
    for (int u = 0; u < 16; u++) {
        int i = tid + u * 256;                 // 0..4095
        int cin = i >> 5, j4 = i & 31;
        int ts = t0 - 8 + j4 * 4;
        int ok = (ts >= 0);
        cp16z(xs + cin * PD + j4 * 4, xbase + (size_t)cin * TT + (ok ? ts : 0), ok ? 16 : 0);
    }
    const float* Wc = g_W + (size_t)chunk * RD;
    {
        #pragma unroll
        for (int u = 0; u < 4; u++) {
            int i = tid + u * 256;             // 0..1023 float4s (32x128)
            int r = i >> 5, c4 = i & 31;
            cp16(ws + r * PD + c4 * 4, Wc + (size_t)i * 4);
        }
        asm volatile("cp.async.commit_group;");
    }
    {
        const float* src = Wc + 32 * CO;
        float* dst = ws + WQ_FLOATS;
        #pragma unroll
        for (int u = 0; u < 4; u++) {
            int i = tid + u * 256;
            int r = i >> 5, c4 = i & 31;
            cp16(dst + r * PD + c4 * 4, src + (size_t)i * 4);
        }
        asm volatile("cp.async.commit_group;");
    }

    float acc[2][8][4];
    #pragma unroll
    for (int m = 0; m < 2; m++)
        #pragma unroll
        for (int n = 0; n < 8; n++)
            #pragma unroll
            for (int q = 0; q < 4; q++) acc[m][n][q] = 0.f;

    // ---- stage 0 peeled: wait x+W0, rna-round x, mma, prefetch stage 2 ----
    asm volatile("cp.async.wait_group 1;");
    __syncthreads();
    #pragma unroll
    for (int u = 0; u < 16; u++) {
        int i = tid + u * 256;
        int cin = i >> 5, j4 = i & 31;
        float4* p = (float4*)(xs + cin * PD + j4 * 4);
        float4 v = *p;
        v.x = to_tf32(v.x); v.y = to_tf32(v.y);
        v.z = to_tf32(v.z); v.w = to_tf32(v.w);
        *p = v;
    }
    __syncthreads();
    conv_stage_mma(ws, xs, acc, 0, 8, lk, lg, wcb, wtb);
    __syncthreads();
    {
        const float* src = Wc + (size_t)2 * 32 * CO;   // stage 2
        #pragma unroll
        for (int u = 0; u < 4; u++) {
            int i = tid + u * 256;
            int r = i >> 5, c4 = i & 31;
            cp16(ws + r * PD + c4 * 4, src + (size_t)i * 4);
        }
        asm volatile("cp.async.commit_group;");
    }

    // ---- stages 1..11 ----
    for (int s = 1; s < 12; s++) {
        if (s < 11) asm volatile("cp.async.wait_group 1;");
        else        asm volatile("cp.async.wait_group 0;");
        __syncthreads();

        int tap = s >> 2, qq = s & 3;
        conv_stage_mma(ws + (s & 1) * WQ_FLOATS, xs, acc, qq, 8 - tap, lk, lg, wcb, wtb);
        __syncthreads();
        if (s < 10) {
            int s2 = s + 2;
            const float* src = Wc + (size_t)((s2 >> 2) * CI + (s2 & 3) * 32) * CO;
            float* dst = ws + (s2 & 1) * WQ_FLOATS;
            #pragma unroll
            for (int u = 0; u < 4; u++) {
                int i = tid + u * 256;
                int r = i >> 5, c4 = i & 31;
                cp16(dst + r * PD + c4 * 4, src + (size_t)i * 4);
            }
            asm volatile("cp.async.commit_group;");
        }
    }

    // ---- epilogue: regs -> smem (reuse xs) -> coalesced gmem ----
    float* os = xs;                           // [128 co][124]
    #pragma unroll
    for (int m = 0; m < 2; m++) {
        int row0 = wcb + m * 16 + lg;
        #pragma unroll
        for (int n = 0; n < 8; n++) {
            int tl = wtb + n * 8 + 2 * lk;
            if (tl < TKC) {
                os[row0 * 124 + tl]           = acc[m][n][0] + biasv[m][0];
                os[row0 * 124 + tl + 1]       = acc[m][n][1] + biasv[m][0];
                os[(row0 + 8) * 124 + tl]     = acc[m][n][2] + biasv[m][1];
                os[(row0 + 8) * 124 + tl + 1] = acc[m][n][3] + biasv[m][1];
            }
        }
    }
    __syncthreads();
    float* ob = out + (size_t)b * CO * TT + t0;
    #pragma unroll
    for (int u = 0; u < 15; u++) {
        int i = tid + u * 256;                // 0..3839 = 128 rows x 30 f4
        int row = i / 30, c4 = i - row * 30;
        float4 v = *(const float4*)(os + row * 124 + c4 * 4);
        *(float4*)(ob + (size_t)row * TT + c4 * 4) = v;
    }
}

// ---------------------------------------------------------------------------
extern "C" void kernel_launch(void* const* d_in, const int* in_sizes, int n_in,
                              void* d_out, int out_size)
{
    const float* x   = (const float*)d_in[0];
    const float* z   = (const float*)d_in[1];
    const float* w1  = (const float*)d_in[2];
    const float* b1  = (const float*)d_in[3];
    const float* w2  = (const float*)d_in[4];
    const float* b2  = (const float*)d_in[5];
    const float* bw1 = (const float*)d_in[6];
    const float* bb1 = (const float*)d_in[7];
    const float* bw2 = (const float*)d_in[8];
    const float* bb2 = (const float*)d_in[9];
    float* out = (float*)d_out;

    cudaFuncSetAttribute(wgen_kernel, cudaFuncAttributeMaxDynamicSharedMemorySize, WG_SMEM);
    cudaFuncSetAttribute(conv_kernel, cudaFuncAttributeMaxDynamicSharedMemorySize, CONV_SMEM);

    prep_kernel<<<NCH / 4, 256>>>(z, w1, b1, bw1, bb1, bw2, bb2);
    wgen_kernel<<<dim3(RD / 128, (NCH + 127) / 128), 256, WG_SMEM>>>(w2, b2);
    conv_kernel<<<NCH, 256, CONV_SMEM>>>(x, out);
}

// round 13
// speedup vs baseline: 1.4672x; 1.4672x over previous
#include <cuda_runtime.h>
#include <cstdint>
#include <cstddef>

#define NB   4
#define ZD   64
#define NK   400
#define TT   48000
#define CI   128
#define CO   128
#define KSZ  3
#define HH   32
#define TKC  120
#define NCH  (NB*NK)                 // 1600
#define RD   (CI*KSZ*CO)             // 49152

// ---------------- device scratch ----------------
__device__ float g_W[(size_t)NCH * RD];      // tf32-rounded weights [chunk][tap*CI+cin][co]
__device__ float g_hv[NCH * HH];
__device__ float g_bias[NCH * CO];

// ---------------- helpers ----------------
__device__ __forceinline__ uint32_t s2u(const void* p) {
    uint32_t a;
    asm("{ .reg .u64 t; cvta.to.shared.u64 t, %1; cvt.u32.u64 %0, t; }" : "=r"(a) : "l"(p));
    return a;
}
__device__ __forceinline__ void cp16(void* d, const void* s) {
    asm volatile("cp.async.cg.shared.global [%0], [%1], 16;" :: "r"(s2u(d)), "l"(s));
}
__device__ __forceinline__ void cp16z(void* d, const void* s, int sz) {
    asm volatile("cp.async.cg.shared.global [%0], [%1], 16, %2;" :: "r"(s2u(d)), "l"(s), "r"(sz));
}
__device__ __forceinline__ float to_tf32(float v) {
    uint32_t r;
    asm("cvt.rna.tf32.f32 %0, %1;" : "=r"(r) : "f"(v));
    return __uint_as_float(r);
}
__device__ __forceinline__ void mma_tf32(float* d, const uint32_t* a, uint32_t b0, uint32_t b1) {
    asm volatile(
        "mma.sync.aligned.m16n8k8.row.col.f32.tf32.tf32.f32 "
        "{%0,%1,%2,%3}, {%4,%5,%6,%7}, {%8,%9}, {%0,%1,%2,%3};"
        : "+f"(d[0]), "+f"(d[1]), "+f"(d[2]), "+f"(d[3])
        : "r"(a[0]), "r"(a[1]), "r"(a[2]), "r"(a[3]), "r"(b0), "r"(b1));
}

// ---------------------------------------------------------------------------
// Kernel 1: MLP hiddens + bias (R9-exact).
// ---------------------------------------------------------------------------
__global__ __launch_bounds__(256) void prep_kernel(
    const float* __restrict__ z,
    const float* __restrict__ w1, const float* __restrict__ b1,
    const float* __restrict__ bw1, const float* __restrict__ bb1,
    const float* __restrict__ bw2, const float* __restrict__ bb2)
{
    __shared__ float w1s[HH * ZD], bw1s[HH * ZD], bw2s[CO * HH];
    __shared__ float zv[4][ZD], hb[4][HH];
    int tid = threadIdx.x;
    for (int i = tid; i < HH * ZD; i += 256) { w1s[i] = w1[i]; bw1s[i] = bw1[i]; }
    for (int i = tid; i < CO * HH; i += 256) bw2s[i] = bw2[i];
    int c0 = blockIdx.x * 4;
    {
        int j = tid & 3, zi = tid >> 2;
        int chunk = c0 + j, b = chunk / NK, kk = chunk % NK;
        zv[j][zi] = z[((size_t)b * ZD + zi) * NK + kk];
    }
    __syncthreads();
    if (tid < 128) {
        int j = tid >> 5, h = tid & 31;
        float s = b1[h];
        #pragma unroll 8
        for (int q = 0; q < ZD; q++) s += w1s[h * ZD + q] * zv[j][q];
        g_hv[(c0 + j) * HH + h] = fmaxf(s, 0.f);
    } else {
        int j = (tid - 128) >> 5, h = (tid - 128) & 31;
        float s = bb1[h];
        #pragma unroll 8
        for (int q = 0; q < ZD; q++) s += bw1s[h * ZD + q] * zv[j][q];
        hb[j][h] = fmaxf(s, 0.f);
    }
    __syncthreads();
    #pragma unroll
    for (int it = 0; it < 2; it++) {
        int idx = tid + it * 256;
        int j = idx >> 7, o = idx & 127;
        float s = bb2[o];
        #pragma unroll
        for (int q = 0; q < HH; q++) s += bw2s[o * HH + q] * hb[j][q];
        g_bias[(c0 + j) * CO + o] = s;
    }
}

// ---------------------------------------------------------------------------
// Kernel 2: weight-gen GEMM, tf32 mma, 3-term split (R9-exact numerics):
//   W ~= w2h*hvh + w2l*hvh + w2h*hvl
// ---------------------------------------------------------------------------
#define WPD 136
#define WG_SMEM (4 * HH * WPD * 4)     // 69632 B dynamic
__global__ __launch_bounds__(256) void wgen_kernel(
    const float* __restrict__ w2, const float* __restrict__ b2)
{
    extern __shared__ __align__(16) float wsm[];
    float* ash = wsm;                   // [k=h][m=r] hi
    float* asl = wsm + HH * WPD;        // lo
    float* bsh = wsm + 2 * HH * WPD;    // [k=h][n=chunk] hi
    float* bsl = wsm + 3 * HH * WPD;    // lo
    int tid = threadIdx.x, lane = tid & 31, wid = tid >> 5;
    int lk = lane & 3, lg = lane >> 2;
    int r0 = blockIdx.x * 128;
    int c0 = blockIdx.y * 128;

    for (int i4 = tid; i4 < 1024; i4 += 256) {
        int r = i4 >> 3, h4 = i4 & 7;
        float4 v = *(const float4*)(w2 + (size_t)(r0 + r) * HH + h4 * 4);
        float f[4] = {v.x, v.y, v.z, v.w};
        #pragma unroll
        for (int q = 0; q < 4; q++) {
            float h = to_tf32(f[q]);
            ash[(h4 * 4 + q) * WPD + r] = h;
            asl[(h4 * 4 + q) * WPD + r] = to_tf32(f[q] - h);
        }
    }
    for (int i4 = tid; i4 < 1024; i4 += 256) {
        int c = i4 >> 3, h4 = i4 & 7;
        int cc = c0 + c; if (cc >= NCH) cc = NCH - 1;
        float4 v = *(const float4*)(g_hv + (size_t)cc * HH + h4 * 4);
        float f[4] = {v.x, v.y, v.z, v.w};
        #pragma unroll
        for (int q = 0; q < 4; q++) {
            float h = to_tf32(f[q]);
            bsh[(h4 * 4 + q) * WPD + c] = h;
            bsl[(h4 * 4 + q) * WPD + c] = to_tf32(f[q] - h);
        }
    }
    __syncthreads();

    int wrb = (wid >> 1) * 32;
    int wcb = (wid & 1) * 64;

    float acc[2][8][4];
    #pragma unroll
    for (int m = 0; m < 2; m++)
        #pragma unroll
        for (int n = 0; n < 8; n++)
            #pragma unroll
            for (int q = 0; q < 4; q++) acc[m][n][q] = 0.f;

    #pragma unroll
    for (int ks = 0; ks < 4; ks++) {
        uint32_t ah[2][4], al[2][4];
        const float* aph = ash + (ks * 8 + lk) * WPD + wrb + lg;
        const float* apl = asl + (ks * 8 + lk) * WPD + wrb + lg;
        #pragma unroll
        for (int m = 0; m < 2; m++) {
            const float* p = aph + m * 16;
            ah[m][0] = __float_as_uint(p[0]);
            ah[m][1] = __float_as_uint(p[8]);
            ah[m][2] = __float_as_uint(p[4 * WPD]);
            ah[m][3] = __float_as_uint(p[4 * WPD + 8]);
            const float* q = apl + m * 16;
            al[m][0] = __float_as_uint(q[0]);
            al[m][1] = __float_as_uint(q[8]);
            al[m][2] = __float_as_uint(q[4 * WPD]);
            al[m][3] = __float_as_uint(q[4 * WPD + 8]);
        }
        const float* bph = bsh + (ks * 8 + lk) * WPD + wcb + lg;
        const float* bpl = bsl + (ks * 8 + lk) * WPD + wcb + lg;
        #pragma unroll
        for (int n = 0; n < 8; n++) {
            uint32_t bh0 = __float_as_uint(bph[n * 8]);
            uint32_t bh1 = __float_as_uint(bph[4 * WPD + n * 8]);
            uint32_t bl0 = __float_as_uint(bpl[n * 8]);
            uint32_t bl1 = __float_as_uint(bpl[4 * WPD + n * 8]);
            #pragma unroll
            for (int m = 0; m < 2; m++) {
                mma_tf32(acc[m][n], ah[m], bh0, bh1);   // hi*hi
                mma_tf32(acc[m][n], al[m], bh0, bh1);   // lo*hi
                mma_tf32(acc[m][n], ah[m], bl0, bl1);   // hi*lo
            }
        }
    }

    float b2v[2][2];
    #pragma unroll
    for (int m = 0; m < 2; m++) {
        b2v[m][0] = b2[r0 + wrb + m * 16 + lg];
        b2v[m][1] = b2[r0 + wrb + m * 16 + lg + 8];
    }
    #pragma unroll
    for (int n = 0; n < 8; n++) {
        int c = c0 + wcb + n * 8 + 2 * lk;
        if (c < NCH) {
            float* base0 = g_W + (size_t)c * RD + r0 + wrb;
            float* base1 = base0 + RD;
            #pragma unroll
            for (int m = 0; m < 2; m++) {
                int rl = m * 16 + lg;
                base0[rl]     = to_tf32(acc[m][n][0] + b2v[m][0]);
                base1[rl]     = to_tf32(acc[m][n][1] + b2v[m][0]);
                base0[rl + 8] = to_tf32(acc[m][n][2] + b2v[m][1]);
                base1[rl + 8] = to_tf32(acc[m][n][3] + b2v[m][1]);
            }
        }
    }
}

// ---------------------------------------------------------------------------
// Kernel 3: conv, tf32 mma. TRIPLE-buffered 16-row W stages (24 stages):
// the buffer freed by stage s-1 is the one stage s+2 needs, so the prefetch
// issues right after the single per-stage sync, fully overlapped with MMA.
// smem = x[128][136] + 3*[16][136] = 95744 B -> 2 CTAs/SM.
// ---------------------------------------------------------------------------
#define PD        136
#define WQ        (16 * PD)                            // 2176 floats
#define XS_FLOATS (128 * PD)                           // 17408
#define CONV_SMEM ((XS_FLOATS + 3 * WQ) * 4)           // 95744 B

__global__ __launch_bounds__(256, 2) void conv_kernel(
    const float* __restrict__ x, float* __restrict__ out)
{
    extern __shared__ __align__(16) float sm[];
    float* xs = sm;                   // [128][PD], col j <-> t = t0 - 8 + j
    float* ws = sm + XS_FLOATS;       // [3][16][PD]

    int tid = threadIdx.x, lane = tid & 31, wid = tid >> 5;
    int lk = lane & 3, lg = lane >> 2;
    int wcb = (wid >> 1) * 32;        // warp co base
    int wtb = (wid & 1) * 64;         // warp t base
    int chunk = blockIdx.x;
    int b = chunk / NK, kk = chunk % NK;
    int t0 = kk * TKC;

    float biasv[2][2];
    #pragma unroll
    for (int m = 0; m < 2; m++) {
        biasv[m][0] = g_bias[(size_t)chunk * CO + wcb + m * 16 + lg];
        biasv[m][1] = g_bias[(size_t)chunk * CO + wcb + m * 16 + lg + 8];
    }

    // ---- prologue: x + W stage0 = G0; W1 = G1; W2 = G2 ----
    const float* xbase = x + (size_t)b * CI * TT;
    #pragma unroll
    for (int u = 0; u < 16; u++) {
        int i = tid + u * 256;                 // 0..4095
        int cin = i >> 5, j4 = i & 31;
        int ts = t0 - 8 + j4 * 4;
        int ok = (ts >= 0);
        cp16z(xs + cin * PD + j4 * 4, xbase + (size_t)cin * TT + (ok ? ts : 0), ok ? 16 : 0);
    }
    const float* Wc = g_W + (size_t)chunk * RD;
    #pragma unroll
    for (int st = 0; st < 3; st++) {
        const float* src = Wc + (size_t)(st * 16) * CO;   // stages 0..2 are tap 0
        float* dst = ws + st * WQ;
        #pragma unroll
        for (int u = 0; u < 2; u++) {
            int i = tid + u * 256;             // 0..511 f4 (16x128)
            int r = i >> 5, c4 = i & 31;
            cp16(dst + r * PD + c4 * 4, src + (size_t)i * 4);
        }
        asm volatile("cp.async.commit_group;");
    }

    float acc[2][8][4];
    #pragma unroll
    for (int m = 0; m < 2; m++)
        #pragma unroll
        for (int n = 0; n < 8; n++)
            #pragma unroll
            for (int q = 0; q < 4; q++) acc[m][n][q] = 0.f;

    // ---- stage 0 peeled: wait x+W0 (allow G1,G2 pending), round x, mma ----
    asm volatile("cp.async.wait_group 2;");
    __syncthreads();
    #pragma unroll
    for (int u = 0; u < 16; u++) {
        int i = tid + u * 256;
        int cin = i >> 5, j4 = i & 31;
        float4* p = (float4*)(xs + cin * PD + j4 * 4);
        float4 v = *p;
        v.x = to_tf32(v.x); v.y = to_tf32(v.y);
        v.z = to_tf32(v.z); v.w = to_tf32(v.w);
        *p = v;
    }
    __syncthreads();
    #pragma unroll
    for (int ks = 0; ks < 2; ks++) {
        uint32_t a[2][4];
        const float* ap = ws + (ks * 8 + lk) * PD + wcb + lg;
        #pragma unroll
        for (int m = 0; m < 2; m++) {
            const float* p = ap + m * 16;
            a[m][0] = __float_as_uint(p[0]);
            a[m][1] = __float_as_uint(p[8]);
            a[m][2] = __float_as_uint(p[4 * PD]);
            a[m][3] = __float_as_uint(p[4 * PD + 8]);
        }
        const float* bp = xs + (ks * 8 + lk) * PD + wtb + lg + 8;
        #pragma unroll
        for (int n = 0; n < 8; n++) {
            uint32_t b0 = __float_as_uint(bp[n * 8]);
            uint32_t b1 = __float_as_uint(bp[4 * PD + n * 8]);
            mma_tf32(acc[0][n], a[0], b0, b1);
            mma_tf32(acc[1][n], a[1], b0, b1);
        }
    }

    // ---- stages 1..23: one sync, prefetch-before-mma ----
    int cur = 1, pf = 0;
    for (int s = 1; s < 24; s++) {
        if (s < 23) asm volatile("cp.async.wait_group 1;");
        else        asm volatile("cp.async.wait_group 0;");
        __syncthreads();      // stage-s data visible; buf pf (= stage s-1's) free

        if (s <= 21) {
            int s2 = s + 2;
            const float* src = Wc + (size_t)((s2 >> 3) * CI + (s2 & 7) * 16) * CO;
            float* dst = ws + pf * WQ;
            #pragma unroll
            for (int u = 0; u < 2; u++) {
                int i = tid + u * 256;
                int r = i >> 5, c4 = i & 31;
                cp16(dst + r * PD + c4 * 4, src + (size_t)i * 4);
            }
            asm volatile("cp.async.commit_group;");
        }

        int tap = s >> 3, q16 = s & 7;
        int jo = 8 - tap;
        const float* wsb = ws + cur * WQ;
        #pragma unroll
        for (int ks = 0; ks < 2; ks++) {
            uint32_t a[2][4];
            const float* ap = wsb + (ks * 8 + lk) * PD + wcb + lg;
            #pragma unroll
            for (int m = 0; m < 2; m++) {
                const float* p = ap + m * 16;
                a[m][0] = __float_as_uint(p[0]);
                a[m][1] = __float_as_uint(p[8]);
                a[m][2] = __float_as_uint(p[4 * PD]);
                a[m][3] = __float_as_uint(p[4 * PD + 8]);
            }
            const float* bp = xs + (q16 * 16 + ks * 8 + lk) * PD + wtb + lg + jo;
            #pragma unroll
            for (int n = 0; n < 8; n++) {
                uint32_t b0 = __float_as_uint(bp[n * 8]);
                uint32_t b1 = __float_as_uint(bp[4 * PD + n * 8]);
                mma_tf32(acc[0][n], a[0], b0, b1);
                mma_tf32(acc[1][n], a[1], b0, b1);
            }
        }
        cur = (cur == 2) ? 0 : cur + 1;
        pf  = (pf  == 2) ? 0 : pf + 1;
    }

    // ---- epilogue: regs -> smem (reuse xs) -> coalesced gmem ----
    __syncthreads();
    float* os = xs;                           // [128 co][124]
    #pragma unroll
    for (int m = 0; m < 2; m++) {
        int row0 = wcb + m * 16 + lg;
        #pragma unroll
        for (int n = 0; n < 8; n++) {
            int tl = wtb + n * 8 + 2 * lk;
            if (tl < TKC) {
                os[row0 * 124 + tl]           = acc[m][n][0] + biasv[m][0];
                os[row0 * 124 + tl + 1]       = acc[m][n][1] + biasv[m][0];
                os[(row0 + 8) * 124 + tl]     = acc[m][n][2] + biasv[m][1];
                os[(row0 + 8) * 124 + tl + 1] = acc[m][n][3] + biasv[m][1];
            }
        }
    }
    __syncthreads();
    float* ob = out + (size_t)b * CO * TT + t0;
    #pragma unroll
    for (int u = 0; u < 15; u++) {
        int i = tid + u * 256;                // 0..3839 = 128 rows x 30 f4
        int row = i / 30, c4 = i - row * 30;
        float4 v = *(const float4*)(os + row * 124 + c4 * 4);
        *(float4*)(ob + (size_t)row * TT + c4 * 4) = v;
    }
}

// ---------------------------------------------------------------------------
extern "C" void kernel_launch(void* const* d_in, const int* in_sizes, int n_in,
                              void* d_out, int out_size)
{
    const float* x   = (const float*)d_in[0];
    const float* z   = (const float*)d_in[1];
    const float* w1  = (const float*)d_in[2];
    const float* b1  = (const float*)d_in[3];
    const float* w2  = (const float*)d_in[4];
    const float* b2  = (const float*)d_in[5];
    const float* bw1 = (const float*)d_in[6];
    const float* bb1 = (const float*)d_in[7];
    const float* bw2 = (const float*)d_in[8];
    const float* bb2 = (const float*)d_in[9];
    float* out = (float*)d_out;

    cudaFuncSetAttribute(wgen_kernel, cudaFuncAttributeMaxDynamicSharedMemorySize, WG_SMEM);
    cudaFuncSetAttribute(conv_kernel, cudaFuncAttributeMaxDynamicSharedMemorySize, CONV_SMEM);

    prep_kernel<<<NCH / 4, 256>>>(z, w1, b1, bw1, bb1, bw2, bb2);
    wgen_kernel<<<dim3(RD / 128, (NCH + 127) / 128), 256, WG_SMEM>>>(w2, b2);
    conv_kernel<<<NCH, 256, CONV_SMEM>>>(x, out);
}